// round 2
// baseline (speedup 1.0000x reference)
#include <cuda_runtime.h>
#include <cuda_bf16.h>
#include <cstdint>
#include <cstddef>

#define BB   64
#define TT   512
#define IND  64
#define HIDD 256

// ---------------- device scratch (static allocs are allowed) ----------------
__device__ __nv_bfloat16 g_Wt[(size_t)HIDD * HIDD * HIDD];  // [i][k][j]  33.5 MB
__device__ float         g_x[BB * HIDD];                    // current state
__device__ __nv_bfloat16 g_r[2][BB * HIDD];                 // ping-pong tanh(x) bf16

// ---------------- helpers ----------------
__device__ __forceinline__ void mma16816(float* c,
    uint32_t a0, uint32_t a1, uint32_t a2, uint32_t a3,
    uint32_t b0, uint32_t b1)
{
    asm volatile(
        "mma.sync.aligned.m16n8k16.row.col.f32.bf16.bf16.f32 "
        "{%0,%1,%2,%3},{%4,%5,%6,%7},{%8,%9},{%0,%1,%2,%3};"
        : "+f"(c[0]), "+f"(c[1]), "+f"(c[2]), "+f"(c[3])
        : "r"(a0), "r"(a1), "r"(a2), "r"(a3), "r"(b0), "r"(b1));
}

__device__ __forceinline__ void cp16(void* dst, const void* src)
{
    uint32_t d = (uint32_t)__cvta_generic_to_shared(dst);
    asm volatile("cp.async.cg.shared.global [%0], [%1], 16;\n" :: "r"(d), "l"(src) : "memory");
}
__device__ __forceinline__ void cp_commit()
{
    asm volatile("cp.async.commit_group;\n" ::: "memory");
}

// ---------------- W conversion: fp32 [i][j][k] -> bf16 [i][k][j] ----------------
__global__ void convert_kernel(const float* __restrict__ W)
{
    __shared__ __nv_bfloat16 tile[32][36];
    const int i   = blockIdx.x;
    const float*         Wi = W    + (size_t)i * HIDD * HIDD;
    __nv_bfloat16*       Oi = g_Wt + (size_t)i * HIDD * HIDD;
    const int tid = threadIdx.x;
    const int r   = tid >> 3;
    const int c4  = (tid & 7) * 4;

    for (int tt = 0; tt < 64; ++tt) {
        const int jt = tt >> 3, kt = tt & 7;
        float4 v = *(const float4*)(Wi + (size_t)(jt * 32 + r) * HIDD + kt * 32 + c4);
        tile[r][c4 + 0] = __float2bfloat16(v.x);
        tile[r][c4 + 1] = __float2bfloat16(v.y);
        tile[r][c4 + 2] = __float2bfloat16(v.z);
        tile[r][c4 + 3] = __float2bfloat16(v.w);
        __syncthreads();
        uint2 ov;
        __nv_bfloat16* op = reinterpret_cast<__nv_bfloat16*>(&ov);
        op[0] = tile[c4 + 0][r];
        op[1] = tile[c4 + 1][r];
        op[2] = tile[c4 + 2][r];
        op[3] = tile[c4 + 3][r];
        *(uint2*)(Oi + (size_t)(kt * 32 + r) * HIDD + jt * 32 + c4) = ov;
        __syncthreads();
    }
}

// ---------------- init: x = x0, r0 = tanh(x0) ----------------
__global__ void init_kernel(const float* __restrict__ x0)
{
    int idx = blockIdx.x * 256 + threadIdx.x;
    if (idx < BB * HIDD) {
        float x = x0[idx];
        g_x[idx] = x;
        g_r[0][idx] = __float2bfloat16(tanhf(x));
    }
}

// ---------------- per-timestep fused kernel ----------------
// grid: 256 CTAs (one per output neuron i), 256 threads (8 warps)
// smem layout (dynamic):
//   rs    : bf16 [64][264]         33792 B  (padded rows: conflict-free A frags)
//   ws    : 2 x 256 rows x 48 B    24576 B  (double-buffered W chunk, 16 j x 256 k)
//   us    : f32 [64][65]           16640 B  (u_t slice, padded)
//   winS  : f32 [64]                 256 B
//   hpart : f32 [8][64]             2048 B
#define RS_OFF   0
#define WS_OFF   33792
#define US_OFF   (33792 + 24576)
#define WIN_OFF  (US_OFF + 16640)
#define HP_OFF   (WIN_OFF + 256)
#define SMEM_STEP (HP_OFF + 2048)

__global__ __launch_bounds__(256, 2) void step_kernel(
    const float* __restrict__ u, const float* __restrict__ noise,
    const float* __restrict__ W_in, const float* __restrict__ b_in,
    float* __restrict__ traj, int t, int par)
{
    extern __shared__ char sm[];
    __nv_bfloat16* rs  = (__nv_bfloat16*)(sm + RS_OFF);
    char*          wsB = sm + WS_OFF;
    float*         us  = (float*)(sm + US_OFF);
    float*         winS= (float*)(sm + WIN_OFF);
    float*         hp  = (float*)(sm + HP_OFF);

    const int i    = blockIdx.x;
    const int tid  = threadIdx.x;
    const int w    = tid >> 5;
    const int lane = tid & 31;
    const int g    = lane >> 2;
    const int tq   = lane & 3;

    // ---- load r (prev rates) into padded smem ----
    {
        const uint4* src = (const uint4*)g_r[par];
        for (int c = tid; c < BB * 32; c += 256) {       // 2048 16B chunks
            int b = c >> 5, q = c & 31;
            *(uint4*)(rs + b * 264 + q * 8) = src[b * 32 + q];
        }
    }
    // ---- load u_t slice [64 b][64 c] ----
    {
        int b = tid >> 2, q = tid & 3;
        const float* up = u + ((size_t)b * TT + t) * IND + q * 16;
        #pragma unroll
        for (int s = 0; s < 4; ++s) {
            float4 v = *(const float4*)(up + s * 4);
            float* d = us + b * 65 + q * 16 + s * 4;
            d[0] = v.x; d[1] = v.y; d[2] = v.z; d[3] = v.w;
        }
    }
    if (tid < IND) winS[tid] = W_in[i * IND + tid];

    // ---- prefetch first two W chunks (16 j x 256 k each) ----
    const __nv_bfloat16* Wt = g_Wt + (size_t)i * HIDD * HIDD;
    auto stage = [&](int jc, int buf) {
        const char* src = (const char*)(Wt + (size_t)tid * HIDD + jc * 16);
        char* dst = wsB + buf * 12288 + tid * 48;
        cp16(dst, src);
        cp16(dst + 16, src + 16);
    };
    stage(0, 0); cp_commit();
    stage(1, 1); cp_commit();

    float acc[4][4][4];
    #pragma unroll
    for (int mt = 0; mt < 4; ++mt)
        #pragma unroll
        for (int nt = 0; nt < 4; ++nt)
            #pragma unroll
            for (int q = 0; q < 4; ++q) acc[mt][nt][q] = 0.f;

    __syncthreads();   // rs/us/winS visible

    // ---- mainloop: S[64 b][256 k] = R[64x256 j] * Wt[i][k][j] ----
    for (int jc = 0; jc < 16; ++jc) {
        asm volatile("cp.async.wait_group 1;\n" ::: "memory");
        __syncthreads();
        const char* wb = wsB + (jc & 1) * 12288;
        uint32_t bfr[4][2];
        #pragma unroll
        for (int nt = 0; nt < 4; ++nt) {
            int n = 32 * w + 8 * nt + g;
            const char* p = wb + n * 48 + 4 * tq;
            bfr[nt][0] = *(const uint32_t*)p;
            bfr[nt][1] = *(const uint32_t*)(p + 16);
        }
        #pragma unroll
        for (int mt = 0; mt < 4; ++mt) {
            const __nv_bfloat16* ar = rs + (16 * mt + g) * 264 + jc * 16 + 2 * tq;
            uint32_t a0 = *(const uint32_t*)ar;
            uint32_t a1 = *(const uint32_t*)(ar + 8 * 264);
            uint32_t a2 = *(const uint32_t*)(ar + 8);
            uint32_t a3 = *(const uint32_t*)(ar + 8 * 264 + 8);
            #pragma unroll
            for (int nt = 0; nt < 4; ++nt)
                mma16816(acc[mt][nt], a0, a1, a2, a3, bfr[nt][0], bfr[nt][1]);
        }
        __syncthreads();
        if (jc + 2 < 16) stage(jc + 2, jc & 1);
        cp_commit();
    }

    // ---- stage 2: h[b] = sum_k S[b][k] * r[b][k] ----
    float p0[4], p1[4];
    #pragma unroll
    for (int mt = 0; mt < 4; ++mt) { p0[mt] = 0.f; p1[mt] = 0.f; }
    #pragma unroll
    for (int mt = 0; mt < 4; ++mt) {
        #pragma unroll
        for (int nt = 0; nt < 4; ++nt) {
            int n = 32 * w + 8 * nt + 2 * tq;
            uint32_t rv0 = *(const uint32_t*)(rs + (16 * mt + g) * 264 + n);
            uint32_t rv1 = *(const uint32_t*)(rs + (16 * mt + 8 + g) * 264 + n);
            float2 f0 = __bfloat1622float2(*(__nv_bfloat162*)&rv0);
            float2 f1 = __bfloat1622float2(*(__nv_bfloat162*)&rv1);
            p0[mt] += acc[mt][nt][0] * f0.x + acc[mt][nt][1] * f0.y;
            p1[mt] += acc[mt][nt][2] * f1.x + acc[mt][nt][3] * f1.y;
        }
    }
    #pragma unroll
    for (int mt = 0; mt < 4; ++mt) {
        p0[mt] += __shfl_xor_sync(0xffffffffu, p0[mt], 1);
        p0[mt] += __shfl_xor_sync(0xffffffffu, p0[mt], 2);
        p1[mt] += __shfl_xor_sync(0xffffffffu, p1[mt], 1);
        p1[mt] += __shfl_xor_sync(0xffffffffu, p1[mt], 2);
    }
    if (tq == 0) {
        #pragma unroll
        for (int mt = 0; mt < 4; ++mt) {
            hp[w * 64 + 16 * mt + g]     = p0[mt];
            hp[w * 64 + 16 * mt + 8 + g] = p1[mt];
        }
    }
    __syncthreads();

    // ---- fused update for column i ----
    if (tid < BB) {
        const int b = tid;
        float h = 0.f;
        #pragma unroll
        for (int ww = 0; ww < 8; ++ww) h += hp[ww * 64 + b];
        float inI = b_in[i];
        #pragma unroll 16
        for (int c = 0; c < IND; ++c) inI += us[b * 65 + c] * winS[c];
        float xo = g_x[b * HIDD + i];
        float nz = noise[((size_t)t * BB + b) * HIDD + i];
        float xn = xo + 0.05f * nz + 0.2f * (-xo + h + inI);
        g_x[b * HIDD + i] = xn;
        traj[((size_t)b * TT + t) * HIDD + i] = xn;
        g_r[par ^ 1][b * HIDD + i] = __float2bfloat16(tanhf(xn));
    }
}

// ---------------- epilogue: x_final copy ----------------
__global__ void finalx_kernel(float* __restrict__ xfin)
{
    int idx = blockIdx.x * 256 + threadIdx.x;
    if (idx < BB * HIDD) xfin[idx] = g_x[idx];
}

// ---------------- epilogue: out = tanh(traj) @ W_out^T + b_out ----------------
#define SMEM_OUT (64 * 260 * 4 + 32 * 256 * 4)
__global__ __launch_bounds__(256) void outgemm_kernel(
    const float* __restrict__ trajg, const float* __restrict__ W_out,
    const float* __restrict__ b_out, float* __restrict__ out)
{
    extern __shared__ char sm[];
    float* wo = (float*)sm;            // [64][260] padded
    float* th = wo + 64 * 260;         // [32][256]
    const int tid = threadIdx.x;

    for (int idx = tid; idx < IND * HIDD; idx += 256) {
        int c = idx >> 8, ii = idx & 255;
        wo[c * 260 + ii] = W_out[idx];
    }
    const size_t r0 = (size_t)blockIdx.x * 32;
    for (int idx = tid; idx < 32 * HIDD; idx += 256) {
        int rl = idx >> 8, ii = idx & 255;
        th[idx] = tanhf(trajg[(r0 + rl) * HIDD + ii]);
    }
    __syncthreads();

    const int c  = tid & 63;
    const int rb = tid >> 6;
    const float bo = b_out[c];
    for (int rr = rb; rr < 32; rr += 4) {
        float accv = bo;
        const float4* tr = (const float4*)(th + rr * HIDD);
        const float4* wr = (const float4*)(wo + c * 260);
        #pragma unroll 8
        for (int i4 = 0; i4 < HIDD / 4; ++i4) {
            float4 a = tr[i4];
            float4 wv = wr[i4];
            accv += a.x * wv.x + a.y * wv.y + a.z * wv.z + a.w * wv.w;
        }
        out[(r0 + rr) * IND + c] = accv;
    }
}

// ---------------- launch ----------------
extern "C" void kernel_launch(void* const* d_in, const int* in_sizes, int n_in,
                              void* d_out, int out_size)
{
    const float* u     = (const float*)d_in[0];  // [B,T,IN]
    const float* x0    = (const float*)d_in[1];  // [B,HID]
    const float* noise = (const float*)d_in[2];  // [T,B,HID]
    const float* W_hh  = (const float*)d_in[3];  // [HID,HID,HID]
    const float* W_in  = (const float*)d_in[4];  // [HID,IN]
    const float* b_in  = (const float*)d_in[5];  // [HID]
    const float* W_out = (const float*)d_in[6];  // [IN,HID]
    const float* b_out = (const float*)d_in[7];  // [IN]

    float* out  = (float*)d_out;                       // [B,T,IN]  2,097,152
    float* xfin = out + (size_t)BB * TT * IND;         // [B,HID]      16,384
    float* traj = xfin + (size_t)BB * HIDD;            // [B,T,HID] 8,388,608

    cudaFuncSetAttribute(step_kernel,   cudaFuncAttributeMaxDynamicSharedMemorySize, SMEM_STEP);
    cudaFuncSetAttribute(outgemm_kernel, cudaFuncAttributeMaxDynamicSharedMemorySize, SMEM_OUT);

    convert_kernel<<<HIDD, 256>>>(W_hh);
    init_kernel<<<64, 256>>>(x0);
    for (int t = 0; t < TT; ++t)
        step_kernel<<<HIDD, 256, SMEM_STEP>>>(u, noise, W_in, b_in, traj, t, t & 1);
    finalx_kernel<<<64, 256>>>(xfin);
    outgemm_kernel<<<(BB * TT) / 32, 256, SMEM_OUT>>>(traj, W_out, b_out, out);
}